// round 1
// baseline (speedup 1.0000x reference)
#include <cuda_runtime.h>
#include <cuda_bf16.h>

// GraphConvolution: out = relu(segment_sum((x @ W)[src] * ew, dst))
// x: [N, 256] f32, W: [256, 64] f32, edge_src/dst: [E] i32, ew: [E] f32
// out: [N, 64] f32
//
// Plan:
//   k1: support = x @ W   (fp32 register-tiled GEMM, support in __device__ scratch)
//   k2: zero out
//   k3: scatter: for each edge, out[dst] += ew * support[src]  (f32 atomics; both
//       arrays are 25.6MB -> L2 resident)
//   k4: relu in place

#define N_NODES_MAX 100000
#define IN_F 256
#define OUT_F 64

__device__ float g_support[N_NODES_MAX * OUT_F];

// ---------------- GEMM: 64x64 block tile, 4x4 thread tile, BK=32 ----------------
#define BM 64
#define BN 64
#define BK 32
#define APAD 68  // row stride for As (floats); 68*4=272B keeps 16B alignment

__global__ __launch_bounds__(256) void gemm_kernel(
    const float* __restrict__ x, const float* __restrict__ w,
    float* __restrict__ sup, int N)
{
    __shared__ float As[BK * APAD];   // As[k][m], padded
    __shared__ float Bs[BK * BN];     // Bs[k][n]

    const int tid = threadIdx.x;            // 0..255
    const int block_row = blockIdx.x * BM;

    const int tm = (tid >> 4) << 2;          // 0,4,...,60
    const int tn = (tid & 15) << 2;          // 0,4,...,60

    float acc[4][4];
#pragma unroll
    for (int i = 0; i < 4; i++)
#pragma unroll
        for (int j = 0; j < 4; j++) acc[i][j] = 0.0f;

    for (int k0 = 0; k0 < IN_F; k0 += BK) {
        // ---- load A tile (64 rows x 32 k) transposed into As[k][m] ----
        // 2048 floats = 512 float4; 256 threads x 2 float4
#pragma unroll
        for (int i = 0; i < 2; i++) {
            int idx = tid * 2 + i;               // 0..511
            int row = idx >> 3;                  // 0..63  (8 float4 per row)
            int kc  = idx & 7;                   // float4 index within BK
            int grow = block_row + row;
            float4 f = make_float4(0.f, 0.f, 0.f, 0.f);
            if (grow < N)
                f = *reinterpret_cast<const float4*>(&x[(size_t)grow * IN_F + k0 + kc * 4]);
            As[(kc * 4 + 0) * APAD + row] = f.x;
            As[(kc * 4 + 1) * APAD + row] = f.y;
            As[(kc * 4 + 2) * APAD + row] = f.z;
            As[(kc * 4 + 3) * APAD + row] = f.w;
        }
        // ---- load B tile (32 k x 64 n) into Bs[k][n] ----
#pragma unroll
        for (int i = 0; i < 2; i++) {
            int idx = tid * 2 + i;               // 0..511
            int krow = idx >> 4;                 // 0..31 (16 float4 per row)
            int nc   = idx & 15;
            float4 f = *reinterpret_cast<const float4*>(&w[(size_t)(k0 + krow) * OUT_F + nc * 4]);
            *reinterpret_cast<float4*>(&Bs[krow * BN + nc * 4]) = f;
        }
        __syncthreads();

#pragma unroll
        for (int k = 0; k < BK; k++) {
            float4 a = *reinterpret_cast<const float4*>(&As[k * APAD + tm]);
            float4 b = *reinterpret_cast<const float4*>(&Bs[k * BN + tn]);
            float av[4] = {a.x, a.y, a.z, a.w};
            float bv[4] = {b.x, b.y, b.z, b.w};
#pragma unroll
            for (int i = 0; i < 4; i++)
#pragma unroll
                for (int j = 0; j < 4; j++)
                    acc[i][j] = fmaf(av[i], bv[j], acc[i][j]);
        }
        __syncthreads();
    }

#pragma unroll
    for (int i = 0; i < 4; i++) {
        int grow = block_row + tm + i;
        if (grow < N) {
#pragma unroll
            for (int j = 0; j < 4; j += 4) {
                float4 v = make_float4(acc[i][0], acc[i][1], acc[i][2], acc[i][3]);
                *reinterpret_cast<float4*>(&sup[(size_t)grow * OUT_F + tn]) = v;
            }
        }
    }
}

// ---------------- zero out ----------------
__global__ void zero_kernel(float4* __restrict__ out, int n4) {
    int i = blockIdx.x * blockDim.x + threadIdx.x;
    if (i < n4) out[i] = make_float4(0.f, 0.f, 0.f, 0.f);
}

// ---------------- scatter: 16 threads per edge, float4 each ----------------
__global__ __launch_bounds__(256) void scatter_kernel(
    const float* __restrict__ sup,
    const int* __restrict__ src, const int* __restrict__ dst,
    const float* __restrict__ ew,
    float* __restrict__ out, int E)
{
    long long idx = (long long)blockIdx.x * blockDim.x + threadIdx.x;
    int e = (int)(idx >> 4);
    if (e >= E) return;
    int q = (int)(idx & 15);

    int s = src[e];
    int d = dst[e];
    float wgt = ew[e];

    float4 v = *reinterpret_cast<const float4*>(&sup[(size_t)s * OUT_F + q * 4]);
    float* o = &out[(size_t)d * OUT_F + q * 4];
    atomicAdd(o + 0, v.x * wgt);
    atomicAdd(o + 1, v.y * wgt);
    atomicAdd(o + 2, v.z * wgt);
    atomicAdd(o + 3, v.w * wgt);
}

// ---------------- relu in place ----------------
__global__ void relu_kernel(float4* __restrict__ out, int n4) {
    int i = blockIdx.x * blockDim.x + threadIdx.x;
    if (i < n4) {
        float4 v = out[i];
        v.x = fmaxf(v.x, 0.f);
        v.y = fmaxf(v.y, 0.f);
        v.z = fmaxf(v.z, 0.f);
        v.w = fmaxf(v.w, 0.f);
        out[i] = v;
    }
}

extern "C" void kernel_launch(void* const* d_in, const int* in_sizes, int n_in,
                              void* d_out, int out_size)
{
    const float* x    = (const float*)d_in[0];
    const float* w    = (const float*)d_in[1];
    const int*   src  = (const int*)d_in[2];
    const int*   dst  = (const int*)d_in[3];
    const float* ew   = (const float*)d_in[4];
    float* out = (float*)d_out;

    const int N = in_sizes[0] / IN_F;
    const int E = in_sizes[2];

    float* sup;
    cudaGetSymbolAddress((void**)&sup, g_support);

    // 1) GEMM
    int gemm_blocks = (N + BM - 1) / BM;
    gemm_kernel<<<gemm_blocks, 256>>>(x, w, sup, N);

    // 2) zero output
    int n4 = (N * OUT_F) / 4;
    zero_kernel<<<(n4 + 255) / 256, 256>>>((float4*)out, n4);

    // 3) scatter-add
    long long threads = (long long)E * 16;
    int sblocks = (int)((threads + 255) / 256);
    scatter_kernel<<<sblocks, 256>>>(sup, src, dst, ew, out, E);

    // 4) relu
    relu_kernel<<<(n4 + 255) / 256, 256>>>((float4*)out, n4);
}

// round 2
// speedup vs baseline: 1.5452x; 1.5452x over previous
#include <cuda_runtime.h>
#include <cuda_bf16.h>

// GraphConvolution: out = relu(segment_sum((x @ W)[src] * ew, dst))
// x: [N, 256] f32, W: [256, 64] f32, edge_src/dst: [E] i32, ew: [E] f32
// out: [N, 64] f32
//
// R1 change: scatter uses red.global.add.v4.f32 (one RED.128 per 4 floats)
// instead of 4 scalar atomicAdd — 4x fewer LSU/REDG issues.

#define N_NODES_MAX 100000
#define IN_F 256
#define OUT_F 64

__device__ float g_support[N_NODES_MAX * OUT_F];

// ---------------- GEMM: 64x64 block tile, 4x4 thread tile, BK=32 ----------------
#define BM 64
#define BN 64
#define BK 32
#define APAD 68  // row stride for As (floats); 68*4=272B keeps 16B alignment

__global__ __launch_bounds__(256) void gemm_kernel(
    const float* __restrict__ x, const float* __restrict__ w,
    float* __restrict__ sup, int N)
{
    __shared__ float As[BK * APAD];   // As[k][m], padded
    __shared__ float Bs[BK * BN];     // Bs[k][n]

    const int tid = threadIdx.x;            // 0..255
    const int block_row = blockIdx.x * BM;

    const int tm = (tid >> 4) << 2;          // 0,4,...,60
    const int tn = (tid & 15) << 2;          // 0,4,...,60

    float acc[4][4];
#pragma unroll
    for (int i = 0; i < 4; i++)
#pragma unroll
        for (int j = 0; j < 4; j++) acc[i][j] = 0.0f;

    for (int k0 = 0; k0 < IN_F; k0 += BK) {
        // ---- load A tile (64 rows x 32 k) transposed into As[k][m] ----
#pragma unroll
        for (int i = 0; i < 2; i++) {
            int idx = tid * 2 + i;               // 0..511
            int row = idx >> 3;                  // 0..63  (8 float4 per row)
            int kc  = idx & 7;                   // float4 index within BK
            int grow = block_row + row;
            float4 f = make_float4(0.f, 0.f, 0.f, 0.f);
            if (grow < N)
                f = *reinterpret_cast<const float4*>(&x[(size_t)grow * IN_F + k0 + kc * 4]);
            As[(kc * 4 + 0) * APAD + row] = f.x;
            As[(kc * 4 + 1) * APAD + row] = f.y;
            As[(kc * 4 + 2) * APAD + row] = f.z;
            As[(kc * 4 + 3) * APAD + row] = f.w;
        }
        // ---- load B tile (32 k x 64 n) into Bs[k][n] ----
#pragma unroll
        for (int i = 0; i < 2; i++) {
            int idx = tid * 2 + i;               // 0..511
            int krow = idx >> 4;                 // 0..31 (16 float4 per row)
            int nc   = idx & 15;
            float4 f = *reinterpret_cast<const float4*>(&w[(size_t)(k0 + krow) * OUT_F + nc * 4]);
            *reinterpret_cast<float4*>(&Bs[krow * BN + nc * 4]) = f;
        }
        __syncthreads();

#pragma unroll
        for (int k = 0; k < BK; k++) {
            float4 a = *reinterpret_cast<const float4*>(&As[k * APAD + tm]);
            float4 b = *reinterpret_cast<const float4*>(&Bs[k * BN + tn]);
            float av[4] = {a.x, a.y, a.z, a.w};
            float bv[4] = {b.x, b.y, b.z, b.w};
#pragma unroll
            for (int i = 0; i < 4; i++)
#pragma unroll
                for (int j = 0; j < 4; j++)
                    acc[i][j] = fmaf(av[i], bv[j], acc[i][j]);
        }
        __syncthreads();
    }

#pragma unroll
    for (int i = 0; i < 4; i++) {
        int grow = block_row + tm + i;
        if (grow < N) {
            float4 v = make_float4(acc[i][0], acc[i][1], acc[i][2], acc[i][3]);
            *reinterpret_cast<float4*>(&sup[(size_t)grow * OUT_F + tn]) = v;
        }
    }
}

// ---------------- zero out ----------------
__global__ void zero_kernel(float4* __restrict__ out, int n4) {
    int i = blockIdx.x * blockDim.x + threadIdx.x;
    if (i < n4) out[i] = make_float4(0.f, 0.f, 0.f, 0.f);
}

// ---------------- scatter: 16 threads per edge, one RED.128 each ----------------
__device__ __forceinline__ void red_add_v4(float* ptr, float4 v) {
    asm volatile("red.global.add.v4.f32 [%0], {%1, %2, %3, %4};"
                 :: "l"(ptr), "f"(v.x), "f"(v.y), "f"(v.z), "f"(v.w)
                 : "memory");
}

__global__ __launch_bounds__(256) void scatter_kernel(
    const float* __restrict__ sup,
    const int* __restrict__ src, const int* __restrict__ dst,
    const float* __restrict__ ew,
    float* __restrict__ out, int E)
{
    long long idx = (long long)blockIdx.x * blockDim.x + threadIdx.x;
    int e = (int)(idx >> 4);
    if (e >= E) return;
    int q = (int)(idx & 15);

    int s = __ldg(&src[e]);
    int d = __ldg(&dst[e]);
    float wgt = __ldg(&ew[e]);

    float4 v = *reinterpret_cast<const float4*>(&sup[(size_t)s * OUT_F + q * 4]);
    v.x *= wgt; v.y *= wgt; v.z *= wgt; v.w *= wgt;
    red_add_v4(&out[(size_t)d * OUT_F + q * 4], v);
}

// ---------------- relu in place ----------------
__global__ void relu_kernel(float4* __restrict__ out, int n4) {
    int i = blockIdx.x * blockDim.x + threadIdx.x;
    if (i < n4) {
        float4 v = out[i];
        v.x = fmaxf(v.x, 0.f);
        v.y = fmaxf(v.y, 0.f);
        v.z = fmaxf(v.z, 0.f);
        v.w = fmaxf(v.w, 0.f);
        out[i] = v;
    }
}

extern "C" void kernel_launch(void* const* d_in, const int* in_sizes, int n_in,
                              void* d_out, int out_size)
{
    const float* x    = (const float*)d_in[0];
    const float* w    = (const float*)d_in[1];
    const int*   src  = (const int*)d_in[2];
    const int*   dst  = (const int*)d_in[3];
    const float* ew   = (const float*)d_in[4];
    float* out = (float*)d_out;

    const int N = in_sizes[0] / IN_F;
    const int E = in_sizes[2];

    float* sup;
    cudaGetSymbolAddress((void**)&sup, g_support);

    // 1) GEMM
    int gemm_blocks = (N + BM - 1) / BM;
    gemm_kernel<<<gemm_blocks, 256>>>(x, w, sup, N);

    // 2) zero output
    int n4 = (N * OUT_F) / 4;
    zero_kernel<<<(n4 + 255) / 256, 256>>>((float4*)out, n4);

    // 3) scatter-add (vectorized RED)
    long long threads = (long long)E * 16;
    int sblocks = (int)((threads + 255) / 256);
    scatter_kernel<<<sblocks, 256>>>(sup, src, dst, ew, out, E);

    // 4) relu
    relu_kernel<<<(n4 + 255) / 256, 256>>>((float4*)out, n4);
}

// round 3
// speedup vs baseline: 1.8098x; 1.1712x over previous
#include <cuda_runtime.h>
#include <cuda_bf16.h>

// GraphConvolution: out = relu(segment_sum((x @ W)[src] * ew, dst))
// R2 change: replace atomic scatter with on-the-fly CSR (counting sort by dst)
// + register-accumulating gather that fuses zero + relu. No atomics in the
// hot aggregation loop.

#define N_NODES_MAX 100000
#define E_MAX       1600000
#define IN_F 256
#define OUT_F 64

#define SCAN_B 512                       // bins per scan block
#define NBLK_MAX ((N_NODES_MAX + SCAN_B - 1) / SCAN_B)

__device__ float              g_support[N_NODES_MAX * OUT_F];
__device__ unsigned long long g_edges[E_MAX];     // packed (src | ew<<32), sorted by dst
__device__ int                g_counts[N_NODES_MAX];
__device__ int                g_offs[N_NODES_MAX];
__device__ int                g_cursor[N_NODES_MAX];
__device__ int                g_blksum[NBLK_MAX];

// ---------------- GEMM: 64x64 block tile, 4x4 thread tile, BK=32 ----------------
#define BM 64
#define BN 64
#define BK 32
#define APAD 68

__global__ __launch_bounds__(256) void gemm_kernel(
    const float* __restrict__ x, const float* __restrict__ w,
    float* __restrict__ sup, int N)
{
    __shared__ float As[BK * APAD];
    __shared__ float Bs[BK * BN];

    const int tid = threadIdx.x;
    const int block_row = blockIdx.x * BM;
    const int tm = (tid >> 4) << 2;
    const int tn = (tid & 15) << 2;

    float acc[4][4];
#pragma unroll
    for (int i = 0; i < 4; i++)
#pragma unroll
        for (int j = 0; j < 4; j++) acc[i][j] = 0.0f;

    for (int k0 = 0; k0 < IN_F; k0 += BK) {
#pragma unroll
        for (int i = 0; i < 2; i++) {
            int idx = tid * 2 + i;
            int row = idx >> 3;
            int kc  = idx & 7;
            int grow = block_row + row;
            float4 f = make_float4(0.f, 0.f, 0.f, 0.f);
            if (grow < N)
                f = *reinterpret_cast<const float4*>(&x[(size_t)grow * IN_F + k0 + kc * 4]);
            As[(kc * 4 + 0) * APAD + row] = f.x;
            As[(kc * 4 + 1) * APAD + row] = f.y;
            As[(kc * 4 + 2) * APAD + row] = f.z;
            As[(kc * 4 + 3) * APAD + row] = f.w;
        }
#pragma unroll
        for (int i = 0; i < 2; i++) {
            int idx = tid * 2 + i;
            int krow = idx >> 4;
            int nc   = idx & 15;
            float4 f = *reinterpret_cast<const float4*>(&w[(size_t)(k0 + krow) * OUT_F + nc * 4]);
            *reinterpret_cast<float4*>(&Bs[krow * BN + nc * 4]) = f;
        }
        __syncthreads();

#pragma unroll
        for (int k = 0; k < BK; k++) {
            float4 a = *reinterpret_cast<const float4*>(&As[k * APAD + tm]);
            float4 b = *reinterpret_cast<const float4*>(&Bs[k * BN + tn]);
            float av[4] = {a.x, a.y, a.z, a.w};
            float bv[4] = {b.x, b.y, b.z, b.w};
#pragma unroll
            for (int i = 0; i < 4; i++)
#pragma unroll
                for (int j = 0; j < 4; j++)
                    acc[i][j] = fmaf(av[i], bv[j], acc[i][j]);
        }
        __syncthreads();
    }

#pragma unroll
    for (int i = 0; i < 4; i++) {
        int grow = block_row + tm + i;
        if (grow < N) {
            float4 v = make_float4(acc[i][0], acc[i][1], acc[i][2], acc[i][3]);
            *reinterpret_cast<float4*>(&sup[(size_t)grow * OUT_F + tn]) = v;
        }
    }
}

// ---------------- CSR build ----------------
__global__ void zero_counts_kernel(int* __restrict__ counts, int N) {
    int i = blockIdx.x * blockDim.x + threadIdx.x;
    if (i < N) counts[i] = 0;
}

__global__ void hist_kernel(const int* __restrict__ dst, int* __restrict__ counts, int E) {
    int e = blockIdx.x * blockDim.x + threadIdx.x;
    if (e < E) atomicAdd(&counts[dst[e]], 1);
}

__global__ __launch_bounds__(SCAN_B) void scan_block_kernel(
    const int* __restrict__ counts, int* __restrict__ offs,
    int* __restrict__ blksum, int N)
{
    __shared__ int sh[SCAN_B];
    int gid = blockIdx.x * SCAN_B + threadIdx.x;
    int v = (gid < N) ? counts[gid] : 0;
    sh[threadIdx.x] = v;
    __syncthreads();
#pragma unroll
    for (int d = 1; d < SCAN_B; d <<= 1) {
        int t = (threadIdx.x >= d) ? sh[threadIdx.x - d] : 0;
        __syncthreads();
        sh[threadIdx.x] += t;
        __syncthreads();
    }
    if (gid < N) offs[gid] = sh[threadIdx.x] - v;   // exclusive within block
    if (threadIdx.x == SCAN_B - 1) blksum[blockIdx.x] = sh[SCAN_B - 1];
}

__global__ __launch_bounds__(256) void scan_top_kernel(int* __restrict__ blksum, int nb) {
    __shared__ int sh[256];
    int v = (threadIdx.x < nb) ? blksum[threadIdx.x] : 0;
    sh[threadIdx.x] = v;
    __syncthreads();
#pragma unroll
    for (int d = 1; d < 256; d <<= 1) {
        int t = (threadIdx.x >= d) ? sh[threadIdx.x - d] : 0;
        __syncthreads();
        sh[threadIdx.x] += t;
        __syncthreads();
    }
    if (threadIdx.x < nb) blksum[threadIdx.x] = sh[threadIdx.x] - v;  // exclusive
}

__global__ void scan_add_kernel(int* __restrict__ offs, const int* __restrict__ blksum,
                                int* __restrict__ cursor, int N)
{
    int gid = blockIdx.x * blockDim.x + threadIdx.x;
    if (gid < N) {
        int o = offs[gid] + blksum[gid / SCAN_B];
        offs[gid] = o;
        cursor[gid] = o;
    }
}

__global__ void sort_scatter_kernel(
    const int* __restrict__ src, const int* __restrict__ dst,
    const float* __restrict__ ew, int* __restrict__ cursor,
    unsigned long long* __restrict__ es, int E)
{
    int e = blockIdx.x * blockDim.x + threadIdx.x;
    if (e < E) {
        int d = dst[e];
        int pos = atomicAdd(&cursor[d], 1);
        unsigned long long p = (unsigned int)src[e]
            | ((unsigned long long)__float_as_uint(ew[e]) << 32);
        es[pos] = p;
    }
}

// ---------------- gather + relu (fused) : 16 lanes per node ----------------
__global__ __launch_bounds__(256) void gather_kernel(
    const float* __restrict__ sup,
    const unsigned long long* __restrict__ es,
    const int* __restrict__ offs, const int* __restrict__ counts,
    float* __restrict__ out, int N)
{
    int group = threadIdx.x >> 4;
    int lane  = threadIdx.x & 15;
    int node = blockIdx.x * 16 + group;
    if (node >= N) return;

    int start = offs[node];
    int deg   = counts[node];
    int end   = start + deg;

    float4 acc = make_float4(0.f, 0.f, 0.f, 0.f);

    int e = start;
    for (; e + 2 <= end; e += 2) {
        unsigned long long p0 = __ldg(&es[e]);
        unsigned long long p1 = __ldg(&es[e + 1]);
        int   s0 = (int)(unsigned int)p0;
        float w0 = __uint_as_float((unsigned int)(p0 >> 32));
        int   s1 = (int)(unsigned int)p1;
        float w1 = __uint_as_float((unsigned int)(p1 >> 32));
        float4 v0 = *reinterpret_cast<const float4*>(&sup[(size_t)s0 * OUT_F + lane * 4]);
        float4 v1 = *reinterpret_cast<const float4*>(&sup[(size_t)s1 * OUT_F + lane * 4]);
        acc.x = fmaf(v0.x, w0, acc.x);
        acc.y = fmaf(v0.y, w0, acc.y);
        acc.z = fmaf(v0.z, w0, acc.z);
        acc.w = fmaf(v0.w, w0, acc.w);
        acc.x = fmaf(v1.x, w1, acc.x);
        acc.y = fmaf(v1.y, w1, acc.y);
        acc.z = fmaf(v1.z, w1, acc.z);
        acc.w = fmaf(v1.w, w1, acc.w);
    }
    if (e < end) {
        unsigned long long p0 = __ldg(&es[e]);
        int   s0 = (int)(unsigned int)p0;
        float w0 = __uint_as_float((unsigned int)(p0 >> 32));
        float4 v0 = *reinterpret_cast<const float4*>(&sup[(size_t)s0 * OUT_F + lane * 4]);
        acc.x = fmaf(v0.x, w0, acc.x);
        acc.y = fmaf(v0.y, w0, acc.y);
        acc.z = fmaf(v0.z, w0, acc.z);
        acc.w = fmaf(v0.w, w0, acc.w);
    }

    acc.x = fmaxf(acc.x, 0.f);
    acc.y = fmaxf(acc.y, 0.f);
    acc.z = fmaxf(acc.z, 0.f);
    acc.w = fmaxf(acc.w, 0.f);
    *reinterpret_cast<float4*>(&out[(size_t)node * OUT_F + lane * 4]) = acc;
}

extern "C" void kernel_launch(void* const* d_in, const int* in_sizes, int n_in,
                              void* d_out, int out_size)
{
    const float* x    = (const float*)d_in[0];
    const float* w    = (const float*)d_in[1];
    const int*   src  = (const int*)d_in[2];
    const int*   dst  = (const int*)d_in[3];
    const float* ew   = (const float*)d_in[4];
    float* out = (float*)d_out;

    const int N = in_sizes[0] / IN_F;
    const int E = in_sizes[2];

    float* sup;                cudaGetSymbolAddress((void**)&sup, g_support);
    unsigned long long* es;    cudaGetSymbolAddress((void**)&es, g_edges);
    int* counts;               cudaGetSymbolAddress((void**)&counts, g_counts);
    int* offs;                 cudaGetSymbolAddress((void**)&offs, g_offs);
    int* cursor;               cudaGetSymbolAddress((void**)&cursor, g_cursor);
    int* blksum;               cudaGetSymbolAddress((void**)&blksum, g_blksum);

    const int nb = (N + SCAN_B - 1) / SCAN_B;

    // 1) GEMM (only needed before gather)
    gemm_kernel<<<(N + BM - 1) / BM, 256>>>(x, w, sup, N);

    // 2) CSR build
    zero_counts_kernel<<<(N + 255) / 256, 256>>>(counts, N);
    hist_kernel<<<(E + 255) / 256, 256>>>(dst, counts, E);
    scan_block_kernel<<<nb, SCAN_B>>>(counts, offs, blksum, N);
    scan_top_kernel<<<1, 256>>>(blksum, nb);
    scan_add_kernel<<<(N + 255) / 256, 256>>>(offs, blksum, cursor, N);
    sort_scatter_kernel<<<(E + 255) / 256, 256>>>(src, dst, ew, cursor, es, E);

    // 3) gather + relu (writes every output element exactly once)
    gather_kernel<<<(N + 15) / 16, 256>>>(sup, es, offs, counts, out, N);
}